// round 15
// baseline (speedup 1.0000x reference)
#include <cuda_runtime.h>
#include <cuda_fp16.h>

// LightGCN layer, gather-form with direct fixed-capacity binning (no scan).
// Two relation chains staggered so complementary phases overlap:
//   zero -> bin1 -> { gather1 (s0)  ||  bin2 (s2) } -> gather2 -> overflow
// bin is atomic/scatter-rate bound; gather is L2-read-BW bound -> they use
// different LTS resources and overlap well, whereas bin||bin and
// gather||gather just time-slice the same pipe (measured R14).
//
// Output layout: [h_user (n_users*64) | h_item (n_items*64)]
// Combined half feature table: rows [0,n_users) = user, [n_users,+n_items) = item.
// Row space: [0, n_items) = item destinations, [n_items, n_total) = user dests.

#define MAX_ROWS  150002
#define CAP       72
#define OVF_CAP   65536
#define D         64

// 16-byte vector of 4 half2 (8 halves) -> single LDG.128 / STG.128.
struct __align__(16) H2x4 { __half2 a, b, c, d; };

__device__ int  g_cursor [MAX_ROWS + 2];         // padded to /4 for int4 zero
__device__ int  g_ovf_count;
__device__ int4 g_ovf    [OVF_CAP];              // (row, src, w_bits, pad)
__device__ int2 g_slots  [(size_t)MAX_ROWS * CAP];
__device__ H2x4 g_feat_h [MAX_ROWS * D / 8];     // 8 halves per entry

// ---------------------------------------------------------------- zero (int4)
__global__ void k_zero(int n4) {
    int i = blockIdx.x * blockDim.x + threadIdx.x;
    if (i < n4) ((int4*)g_cursor)[i] = make_int4(0, 0, 0, 0);
    if (i == 0) g_ovf_count = 0;
}

// ------------------------------------------- fused convert + direct binning
// One relation per launch: converts its feat half and bins its edges.
__device__ __forceinline__ void bin_edge(int d, int s, float w) {
    int pos = atomicAdd(&g_cursor[d], 1);
    if (pos < CAP) {
        g_slots[(size_t)d * CAP + pos] = make_int2(s, __float_as_int(w));
    } else {
        int o = atomicAdd(&g_ovf_count, 1);
        if (o < OVF_CAP) g_ovf[o] = make_int4(d, s, __float_as_int(w), 0);
    }
}

__global__ void k_bin(const float4* __restrict__ feat,
                      int n8, int feat_off,
                      const int*   __restrict__ src,
                      const int*   __restrict__ dst,
                      const float* __restrict__ norm,
                      int E, int dst_off, int src_off) {
    int i = blockIdx.x * blockDim.x + threadIdx.x;

    // ---- convert part (fp32 -> fp16 table, 8 floats -> one H2x4)
    if (i < n8) {
        const float4* p = feat + 2 * (size_t)i;
        float4 a = p[0];
        float4 b = p[1];
        H2x4 o;
        o.a = __floats2half2_rn(a.x, a.y);
        o.b = __floats2half2_rn(a.z, a.w);
        o.c = __floats2half2_rn(b.x, b.y);
        o.d = __floats2half2_rn(b.z, b.w);
        g_feat_h[feat_off + i] = o;
    }

    // ---- binning part (4 edges per thread via int4/float4)
    int nq = E >> 2;
    if (i < nq) {
        int4   s4 = ((const int4*)src)[i];
        int4   d4 = ((const int4*)dst)[i];
        float4 w4 = ((const float4*)norm)[i];
        bin_edge(dst_off + d4.x, src_off + s4.x, w4.x);
        bin_edge(dst_off + d4.y, src_off + s4.y, w4.y);
        bin_edge(dst_off + d4.z, src_off + s4.z, w4.z);
        bin_edge(dst_off + d4.w, src_off + s4.w, w4.w);
    } else {
        int t = i - nq;
        int tail = E & 3;
        if (t < tail) {
            int e = (nq << 2) + t;
            bin_edge(dst_off + dst[e], src_off + src[e], norm[e]);
        }
    }
}

// ------------------------------------------- gather: one warp per output row
// 4 edges per step; each 8-lane group loads its own slot entry directly.
// Row range [row_begin, row_end) per launch. Body identical to the baseline
// (no stores to read-only state -- R12 lesson).
__global__ void __launch_bounds__(256)
k_gather(float* __restrict__ out, int row_begin, int row_end,
         int n_items, int n_users) {
    int gid = blockIdx.x * blockDim.x + threadIdx.x;
    int row = row_begin + (gid >> 5);
    if (row >= row_end) return;

    int lane  = threadIdx.x & 31;
    int group = lane >> 3;       // which of 4 edges per step
    int c     = lane & 7;        // 16B chunk within the 128B half row

    float* orow;
    if (row < n_items) {
        orow = out + ((size_t)(n_users + row) << 6);   // h_item
    } else {
        orow = out + ((size_t)(row - n_items) << 6);   // h_user
    }

    int cnt = __ldg(&g_cursor[row]);
    if (cnt > CAP) cnt = CAP;                    // overflow handled later
    const int2* slots = g_slots + (size_t)row * CAP;

    float acc[8];
    #pragma unroll
    for (int k = 0; k < 8; k++) acc[k] = 0.f;

    #pragma unroll 4
    for (int e0 = 0; e0 < cnt; e0 += 4) {
        int e = e0 + group;
        int2 ent = (e < cnt) ? __ldg(&slots[e]) : make_int2(0, 0);
        float w = __int_as_float(ent.y);         // 0 for padded -> no-op
        H2x4 hv = g_feat_h[(size_t)ent.x * 8 + c];
        float2 f0 = __half22float2(hv.a);
        float2 f1 = __half22float2(hv.b);
        float2 f2 = __half22float2(hv.c);
        float2 f3 = __half22float2(hv.d);
        acc[0] += f0.x * w;  acc[1] += f0.y * w;
        acc[2] += f1.x * w;  acc[3] += f1.y * w;
        acc[4] += f2.x * w;  acc[5] += f2.y * w;
        acc[6] += f3.x * w;  acc[7] += f3.y * w;
    }

    // reduce 4 groups -> lanes 0-7
    #pragma unroll
    for (int k = 0; k < 8; k++) {
        acc[k] += __shfl_xor_sync(0xffffffffu, acc[k], 8);
        acc[k] += __shfl_xor_sync(0xffffffffu, acc[k], 16);
    }

    if (lane < 8) {
        float4* p = (float4*)(orow + (c << 3));
        p[0] = make_float4(acc[0], acc[1], acc[2], acc[3]);
        p[1] = make_float4(acc[4], acc[5], acc[6], acc[7]);
    }
}

// ------------------------------------------- overflow fixup (cold path)
__global__ void k_overflow(float* __restrict__ out, int n_items, int n_users) {
    int n = g_ovf_count;
    if (n > OVF_CAP) n = OVF_CAP;
    if (n == 0) return;
    const __half* ft = (const __half*)g_feat_h;
    for (int idx = threadIdx.x; idx < n * D; idx += blockDim.x) {
        int e = idx >> 6;
        int f = idx & 63;
        int4 ent = g_ovf[e];
        int row = ent.x;
        float w = __int_as_float(ent.z);
        float v = __half2float(ft[(size_t)ent.y * D + f]);
        float* orow = (row < n_items)
                    ? out + ((size_t)(n_users + row) << 6)
                    : out + ((size_t)(row - n_items) << 6);
        atomicAdd(&orow[f], v * w);
    }
}

// ---------------------------------------------------------------- launch
extern "C" void kernel_launch(void* const* d_in, const int* in_sizes, int n_in,
                              void* d_out, int out_size) {
    const float* user_feat = (const float*)d_in[0];
    const float* item_feat = (const float*)d_in[1];
    const float* norm_ui   = (const float*)d_in[2];
    const float* norm_iu   = (const float*)d_in[3];
    const int*   ui_src    = (const int*)d_in[4];
    const int*   ui_dst    = (const int*)d_in[5];
    const int*   iu_src    = (const int*)d_in[6];
    const int*   iu_dst    = (const int*)d_in[7];

    float* out = (float*)d_out;

    int n_users = in_sizes[0] / D;
    int n_items = in_sizes[1] / D;
    int E_ui    = in_sizes[4];
    int E_iu    = in_sizes[6];
    int n_total = n_items + n_users;

    int n8u = n_users * D / 8;
    int n8i = n_items * D / 8;

    // One-time side stream + events (host objects only; per-call submitted
    // work is identical on every call -> deterministic, capture-legal).
    static cudaStream_t s2 = nullptr;
    static cudaEvent_t ev1 = nullptr, evJ = nullptr;
    if (s2 == nullptr) {
        cudaStreamCreateWithFlags(&s2, cudaStreamNonBlocking);
        cudaEventCreateWithFlags(&ev1, cudaEventDisableTiming);
        cudaEventCreateWithFlags(&evJ, cudaEventDisableTiming);
    }

    // 1. zero cursors + overflow counter
    int n4 = (n_total + 3) / 4;
    k_zero<<<(n4 + 255) / 256, 256>>>(n4);

    // 2. bin1: convert user feats + bin ui edges (items rows)
    {
        int nq = (E_ui >> 2) + (E_ui & 3);
        int work = (n8u > nq) ? n8u : nq;
        k_bin<<<(work + 255) / 256, 256>>>((const float4*)user_feat, n8u, 0,
                                           ui_src, ui_dst, norm_ui,
                                           E_ui, /*dst_off=*/0, /*src_off=*/0);
    }
    cudaEventRecord(ev1, 0);
    cudaStreamWaitEvent(s2, ev1, 0);

    // 3a. gather1 (s0): item rows — L2-read-bound
    {
        long long th = (long long)n_items * 32;
        k_gather<<<(int)((th + 255) / 256), 256>>>(out, 0, n_items,
                                                   n_items, n_users);
    }

    // 3b. bin2 (s2): convert item feats + bin iu edges — atomic-rate-bound
    //     (complementary resource -> overlaps with gather1)
    {
        int nq = (E_iu >> 2) + (E_iu & 3);
        int work = (n8i > nq) ? n8i : nq;
        k_bin<<<(work + 255) / 256, 256, 0, s2>>>((const float4*)item_feat,
                                                  n8i, n8u,
                                                  iu_src, iu_dst, norm_iu,
                                                  E_iu, /*dst_off=*/n_items,
                                                  /*src_off=*/n_users);
    }

    // 4. gather2 (s2): user rows
    {
        long long th = (long long)n_users * 32;
        k_gather<<<(int)((th + 255) / 256), 256, 0, s2>>>(out, n_items, n_total,
                                                          n_items, n_users);
    }

    // Join: s0 waits for chain 2, then overflow fixup.
    cudaEventRecord(evJ, s2);
    cudaStreamWaitEvent(0, evJ, 0);
    k_overflow<<<1, 256>>>(out, n_items, n_users);
}

// round 17
// speedup vs baseline: 1.0054x; 1.0054x over previous
#include <cuda_runtime.h>
#include <cuda_fp16.h>

// LightGCN layer, gather-form with direct fixed-capacity binning (no scan).
// Two fully independent relation chains on two streams:
//   s0: fork -> zero(item rows) -> bin ui -> gather items
//   s2: (wait fork) zero(user rows) -> bin iu -> gather users
//   join -> overflow fixup (also resets the overflow counter for next call)
// Capture-legal fork/join: evFork recorded on s0 BEFORE any s2 launch
// (required during stream capture), evJoin from s2 back to s0.
//
// Output layout: [h_user (n_users*64) | h_item (n_items*64)]
// Combined half feature table: rows [0,n_users) = user, [n_users,+n_items) = item.
// Row space: [0, n_items) = item destinations, [n_items, n_total) = user dests.

#define MAX_ROWS  150002
#define CAP       72
#define OVF_CAP   65536
#define D         64

// 16-byte vector of 4 half2 (8 halves) -> single LDG.128 / STG.128.
struct __align__(16) H2x4 { __half2 a, b, c, d; };

__device__ int  g_cursor [MAX_ROWS + 2];
__device__ int  g_ovf_count;                     // reset by k_overflow tail
__device__ int4 g_ovf    [OVF_CAP];              // (row, src, w_bits, pad)
__device__ int2 g_slots  [(size_t)MAX_ROWS * CAP];
__device__ H2x4 g_feat_h [MAX_ROWS * D / 8];     // 8 halves per entry

// ------------------------------------------- zero a cursor row range
__global__ void k_zero_range(int begin, int count) {
    int i = blockIdx.x * blockDim.x + threadIdx.x;
    if (i < count) g_cursor[begin + i] = 0;
}

// ------------------------------------------- fused convert + direct binning
// One relation per launch: converts its feat half and bins its edges.
__device__ __forceinline__ void bin_edge(int d, int s, float w) {
    int pos = atomicAdd(&g_cursor[d], 1);
    if (pos < CAP) {
        g_slots[(size_t)d * CAP + pos] = make_int2(s, __float_as_int(w));
    } else {
        int o = atomicAdd(&g_ovf_count, 1);
        if (o < OVF_CAP) g_ovf[o] = make_int4(d, s, __float_as_int(w), 0);
    }
}

__global__ void k_bin(const float4* __restrict__ feat,
                      int n8, int feat_off,
                      const int*   __restrict__ src,
                      const int*   __restrict__ dst,
                      const float* __restrict__ norm,
                      int E, int dst_off, int src_off) {
    int i = blockIdx.x * blockDim.x + threadIdx.x;

    // ---- convert part (fp32 -> fp16 table, 8 floats -> one H2x4)
    if (i < n8) {
        const float4* p = feat + 2 * (size_t)i;
        float4 a = p[0];
        float4 b = p[1];
        H2x4 o;
        o.a = __floats2half2_rn(a.x, a.y);
        o.b = __floats2half2_rn(a.z, a.w);
        o.c = __floats2half2_rn(b.x, b.y);
        o.d = __floats2half2_rn(b.z, b.w);
        g_feat_h[feat_off + i] = o;
    }

    // ---- binning part (4 edges per thread via int4/float4)
    int nq = E >> 2;
    if (i < nq) {
        int4   s4 = ((const int4*)src)[i];
        int4   d4 = ((const int4*)dst)[i];
        float4 w4 = ((const float4*)norm)[i];
        bin_edge(dst_off + d4.x, src_off + s4.x, w4.x);
        bin_edge(dst_off + d4.y, src_off + s4.y, w4.y);
        bin_edge(dst_off + d4.z, src_off + s4.z, w4.z);
        bin_edge(dst_off + d4.w, src_off + s4.w, w4.w);
    } else {
        int t = i - nq;
        int tail = E & 3;
        if (t < tail) {
            int e = (nq << 2) + t;
            bin_edge(dst_off + dst[e], src_off + src[e], norm[e]);
        }
    }
}

// ------------------------------------------- gather: one warp per output row
// 4 edges per step; each 8-lane group loads its own slot entry directly.
// Row range [row_begin, row_end) per launch. Body identical to the baseline
// (no stores to read-only state -- R12 lesson).
__global__ void __launch_bounds__(256)
k_gather(float* __restrict__ out, int row_begin, int row_end,
         int n_items, int n_users) {
    int gid = blockIdx.x * blockDim.x + threadIdx.x;
    int row = row_begin + (gid >> 5);
    if (row >= row_end) return;

    int lane  = threadIdx.x & 31;
    int group = lane >> 3;       // which of 4 edges per step
    int c     = lane & 7;        // 16B chunk within the 128B half row

    float* orow;
    if (row < n_items) {
        orow = out + ((size_t)(n_users + row) << 6);   // h_item
    } else {
        orow = out + ((size_t)(row - n_items) << 6);   // h_user
    }

    int cnt = __ldg(&g_cursor[row]);
    if (cnt > CAP) cnt = CAP;                    // overflow handled later
    const int2* slots = g_slots + (size_t)row * CAP;

    float acc[8];
    #pragma unroll
    for (int k = 0; k < 8; k++) acc[k] = 0.f;

    #pragma unroll 4
    for (int e0 = 0; e0 < cnt; e0 += 4) {
        int e = e0 + group;
        int2 ent = (e < cnt) ? __ldg(&slots[e]) : make_int2(0, 0);
        float w = __int_as_float(ent.y);         // 0 for padded -> no-op
        H2x4 hv = g_feat_h[(size_t)ent.x * 8 + c];
        float2 f0 = __half22float2(hv.a);
        float2 f1 = __half22float2(hv.b);
        float2 f2 = __half22float2(hv.c);
        float2 f3 = __half22float2(hv.d);
        acc[0] += f0.x * w;  acc[1] += f0.y * w;
        acc[2] += f1.x * w;  acc[3] += f1.y * w;
        acc[4] += f2.x * w;  acc[5] += f2.y * w;
        acc[6] += f3.x * w;  acc[7] += f3.y * w;
    }

    // reduce 4 groups -> lanes 0-7
    #pragma unroll
    for (int k = 0; k < 8; k++) {
        acc[k] += __shfl_xor_sync(0xffffffffu, acc[k], 8);
        acc[k] += __shfl_xor_sync(0xffffffffu, acc[k], 16);
    }

    if (lane < 8) {
        float4* p = (float4*)(orow + (c << 3));
        p[0] = make_float4(acc[0], acc[1], acc[2], acc[3]);
        p[1] = make_float4(acc[4], acc[5], acc[6], acc[7]);
    }
}

// ------------------------------------------- overflow fixup (cold path)
// Applies overflow edges with atomics, then resets the counter so the next
// call starts from zero (module-load zero covers the very first call).
__global__ void k_overflow(float* __restrict__ out, int n_items, int n_users) {
    int n = g_ovf_count;
    if (n > OVF_CAP) n = OVF_CAP;
    if (n > 0) {
        const __half* ft = (const __half*)g_feat_h;
        for (int idx = threadIdx.x; idx < n * D; idx += blockDim.x) {
            int e = idx >> 6;
            int f = idx & 63;
            int4 ent = g_ovf[e];
            int row = ent.x;
            float w = __int_as_float(ent.z);
            float v = __half2float(ft[(size_t)ent.y * D + f]);
            float* orow = (row < n_items)
                        ? out + ((size_t)(n_users + row) << 6)
                        : out + ((size_t)(row - n_items) << 6);
            atomicAdd(&orow[f], v * w);
        }
        __syncthreads();
        if (threadIdx.x == 0) g_ovf_count = 0;
    }
}

// ---------------------------------------------------------------- launch
extern "C" void kernel_launch(void* const* d_in, const int* in_sizes, int n_in,
                              void* d_out, int out_size) {
    const float* user_feat = (const float*)d_in[0];
    const float* item_feat = (const float*)d_in[1];
    const float* norm_ui   = (const float*)d_in[2];
    const float* norm_iu   = (const float*)d_in[3];
    const int*   ui_src    = (const int*)d_in[4];
    const int*   ui_dst    = (const int*)d_in[5];
    const int*   iu_src    = (const int*)d_in[6];
    const int*   iu_dst    = (const int*)d_in[7];

    float* out = (float*)d_out;

    int n_users = in_sizes[0] / D;
    int n_items = in_sizes[1] / D;
    int E_ui    = in_sizes[4];
    int E_iu    = in_sizes[6];
    int n_total = n_items + n_users;

    int n8u = n_users * D / 8;
    int n8i = n_items * D / 8;

    // One-time side stream + fork/join events (host objects only; per-call
    // submitted work is identical on every call -> deterministic).
    static cudaStream_t s2 = nullptr;
    static cudaEvent_t evFork = nullptr, evJoin = nullptr;
    if (s2 == nullptr) {
        cudaStreamCreateWithFlags(&s2, cudaStreamNonBlocking);
        cudaEventCreateWithFlags(&evFork, cudaEventDisableTiming);
        cudaEventCreateWithFlags(&evJoin, cudaEventDisableTiming);
    }

    // Fork s2 from the capture-origin stream BEFORE any s2 work (required
    // for stream-capture legality; R16 lesson).
    cudaEventRecord(evFork, 0);
    cudaStreamWaitEvent(s2, evFork, 0);

    // ---- chain 1 (s0): item rows
    k_zero_range<<<(n_items + 255) / 256, 256>>>(0, n_items);
    {
        int nq = (E_ui >> 2) + (E_ui & 3);
        int work = (n8u > nq) ? n8u : nq;
        k_bin<<<(work + 255) / 256, 256>>>((const float4*)user_feat, n8u, 0,
                                           ui_src, ui_dst, norm_ui,
                                           E_ui, /*dst_off=*/0, /*src_off=*/0);
        long long th = (long long)n_items * 32;
        k_gather<<<(int)((th + 255) / 256), 256>>>(out, 0, n_items,
                                                   n_items, n_users);
    }

    // ---- chain 2 (s2): user rows (fully independent of chain 1)
    k_zero_range<<<(n_users + 255) / 256, 256, 0, s2>>>(n_items, n_users);
    {
        int nq = (E_iu >> 2) + (E_iu & 3);
        int work = (n8i > nq) ? n8i : nq;
        k_bin<<<(work + 255) / 256, 256, 0, s2>>>((const float4*)item_feat,
                                                  n8i, n8u,
                                                  iu_src, iu_dst, norm_iu,
                                                  E_iu, /*dst_off=*/n_items,
                                                  /*src_off=*/n_users);
        long long th = (long long)n_users * 32;
        k_gather<<<(int)((th + 255) / 256), 256, 0, s2>>>(out, n_items, n_total,
                                                          n_items, n_users);
    }

    // Join: s0 waits for chain 2, then overflow fixup (resets counter).
    cudaEventRecord(evJoin, s2);
    cudaStreamWaitEvent(0, evJoin, 0);
    k_overflow<<<1, 256>>>(out, n_items, n_users);
}